// round 16
// baseline (speedup 1.0000x reference)
#include <cuda_runtime.h>
#include <cuda_bf16.h>
#include <math.h>

#define Fn 500
#define Hn 2000
#define FH 2500
#define Dn 64
#define Bn 4096
#define NW 80            // bitmask words per row
#define NJC 4            // j-chunks of 640
#define FSPLIT 10
#define FCH 50           // f per split
#define TFQ 10           // f per tile

// Scratch
__device__ __align__(16) float g_U[Fn * 128];     // [P1=wu*a^2 | P2=wu*a]
__device__ __align__(16) float g_V[FH * 128];     // [b | b^2]
__device__ float g_B[FH];
__device__ __align__(16) float g_pre_f[Fn * Dn];
__device__ unsigned g_mbits[Fn * NW];
__device__ __align__(16) float g_ctx_part[NJC][Fn][Dn];
__device__ float g_ssum_part[Fn][NJC];
__device__ __align__(16) float g_ctx[Fn * Dn];
__device__ __align__(16) float g_out_part[FSPLIT][Bn][Dn];   // 10.5MB partials
__device__ int g_maxa_bits = 0;   // idempotent across replays (same inputs)
__device__ int g_maxb_bits = 0;
__device__ float g_sink;          // keeps prefetch loads alive

typedef unsigned long long ull;
__device__ __forceinline__ ull pk2(float a, float b) {
    ull r; asm("mov.b64 %0, {%1,%2};" : "=l"(r) : "f"(a), "f"(b)); return r;
}
__device__ __forceinline__ void upk2(ull v, float& a, float& b) {
    asm("mov.b64 {%0,%1}, %2;" : "=f"(a), "=f"(b) : "l"(v));
}
__device__ __forceinline__ ull f2fma(ull a, ull b, ull c) {
    ull d; asm("fma.rn.f32x2 %0, %1, %2, %3;" : "=l"(d) : "l"(a), "l"(b), "l"(c)); return d;
}
__device__ __forceinline__ const float* full_row(const float* feat,
                                                 const float* hid, int j) {
    return (j < Fn) ? (feat + j * Dn) : (hid + (j - Fn) * Dn);
}

// ---------------------------------------------------------------------------
// K1: blk 0..624   : pre_w rows -> V=[b,b^2], B_j, maxb
//     blk 625..749 : pre_f rows -> U, pre_f, maxa
//     blk 750..906 : mask -> bitmask (float4, MLP 8)
// ---------------------------------------------------------------------------
__global__ __launch_bounds__(256) void k1(const float* __restrict__ feat,
                                          const float* __restrict__ hid,
                                          const float* __restrict__ Ww,
                                          const float* __restrict__ bw,
                                          const float* __restrict__ Wu,
                                          const float* __restrict__ mask)
{
    __shared__ float sx[4][Dn];
    __shared__ float s_red[8];
    __shared__ float s_rmax[8];

    const int blk  = blockIdx.x;
    const int tid  = threadIdx.x;
    const int g    = tid >> 6;
    const int a    = tid & 63;
    const int wid  = tid >> 5;
    const int lane = tid & 31;

    if (blk < 625) {
        const int row = blk * 4 + g;                    // j: 0..2499
        float v = (row < Fn) ? feat[row * Dn + a] : hid[(row - Fn) * Dn + a];
        sx[g][a] = v;
        __syncthreads();
        float bacc = 0.f;
        #pragma unroll
        for (int k = 0; k < Dn; k++)
            bacc += sx[g][k] * __ldg(&Ww[(Dn + k) * Dn + a]);
        const float wua = __ldg(&Wu[a]);
        const float b2 = bacc * bacc;
        g_V[row * 128 + a]      = bacc;
        g_V[row * 128 + 64 + a] = b2;
        float term = wua * (bacc - bacc * b2 * 0.33333334f);
        float mm = fabsf(bacc);
        #pragma unroll
        for (int off = 16; off > 0; off >>= 1) {
            term += __shfl_xor_sync(0xffffffffu, term, off);
            mm = fmaxf(mm, __shfl_xor_sync(0xffffffffu, mm, off));
        }
        if (lane == 0) { s_red[wid] = term; s_rmax[wid] = mm; }
        __syncthreads();
        if (tid < 4)
            g_B[blk * 4 + tid] = s_red[2 * tid] + s_red[2 * tid + 1];
        if (tid == 0) {
            float mx = fmaxf(fmaxf(s_rmax[0], s_rmax[1]),
                             fmaxf(s_rmax[2], s_rmax[3]));
            mx = fmaxf(mx, fmaxf(fmaxf(s_rmax[4], s_rmax[5]),
                                 fmaxf(s_rmax[6], s_rmax[7])));
            atomicMax(&g_maxb_bits, __float_as_int(mx));
        }
    } else if (blk < 750) {
        const int row = (blk - 625) * 4 + g;            // i: 0..499
        sx[g][a] = feat[row * Dn + a];
        __syncthreads();
        float av = __ldg(&bw[a]);
        #pragma unroll
        for (int k = 0; k < Dn; k++)
            av += sx[g][k] * __ldg(&Ww[k * Dn + a]);
        const float wua = __ldg(&Wu[a]);
        g_pre_f[row * Dn + a]   = av;
        g_U[row * 128 + a]      = wua * av * av;
        g_U[row * 128 + 64 + a] = wua * av;
        float mm = fabsf(av);
        #pragma unroll
        for (int off = 16; off > 0; off >>= 1)
            mm = fmaxf(mm, __shfl_xor_sync(0xffffffffu, mm, off));
        if (lane == 0) s_rmax[wid] = mm;
        __syncthreads();
        if (tid == 0) {
            float mx = fmaxf(fmaxf(s_rmax[0], s_rmax[1]),
                             fmaxf(s_rmax[2], s_rmax[3]));
            mx = fmaxf(mx, fmaxf(fmaxf(s_rmax[4], s_rmax[5]),
                                 fmaxf(s_rmax[6], s_rmax[7])));
            atomicMax(&g_maxa_bits, __float_as_int(mx));
        }
    } else {
        const int gw = (blk - 750) * 256 + tid;         // word index
        if (gw < Fn * NW) {
            const int i = gw / NW;
            const int w = gw - i * NW;
            const int j0 = w * 32;
            const float* mrow = mask + (size_t)i * FH;
            unsigned word = 0;
            if (j0 + 32 <= FH) {
                const float4* m4 = (const float4*)(mrow + j0);
                #pragma unroll
                for (int q = 0; q < 8; q++) {
                    float4 v = __ldg(&m4[q]);
                    if (v.x != 0.f) word |= (1u << (q * 4 + 0));
                    if (v.y != 0.f) word |= (1u << (q * 4 + 1));
                    if (v.z != 0.f) word |= (1u << (q * 4 + 2));
                    if (v.w != 0.f) word |= (1u << (q * 4 + 3));
                }
            } else {
                for (int t = 0; t < 32; t++) {
                    int j = j0 + t;
                    if (j < FH && __ldg(&mrow[j]) != 0.0f) word |= (1u << t);
                }
            }
            g_mbits[gw] = word;
        }
    }
}

// ---------------------------------------------------------------------------
// K2: blk 0..1999 : attention (500 i x 4 j-chunks) — verbatim, measured fast
//     blk 2000..2511 : stream `values` through L2 (overlapped prefetch)
// ---------------------------------------------------------------------------
__global__ __launch_bounds__(128) void k2(const float* __restrict__ values,
                                          const float* __restrict__ feat,
                                          const float* __restrict__ hid,
                                          const float* __restrict__ Wu)
{
    __shared__ __align__(16) float s_U[128];
    __shared__ __align__(16) float s_pf[Dn];
    __shared__ __align__(16) float s_wu[Dn];
    __shared__ unsigned s_words[20];
    __shared__ unsigned short s_jlist[640];
    __shared__ float s_elist[640];
    __shared__ int   s_warpbase[5];
    __shared__ float s_wsum[4];
    __shared__ float s_part[2][Dn];
    __shared__ float s_swu;
    __shared__ int   s_exact;

    const int tid  = threadIdx.x;
    const int wid  = tid >> 5;
    const int lane = tid & 31;

    if (blockIdx.x >= 2000) {
        const float4* src = (const float4*)values;
        float s0 = 0.f, s1 = 0.f, s2 = 0.f, s3 = 0.f;
        int idx = (blockIdx.x - 2000) * 128 + tid;
        for (; idx + 3 * 65536 < 512000; idx += 4 * 65536) {
            float4 v0 = __ldg(&src[idx]);
            float4 v1 = __ldg(&src[idx + 65536]);
            float4 v2 = __ldg(&src[idx + 2 * 65536]);
            float4 v3 = __ldg(&src[idx + 3 * 65536]);
            s0 += (v0.x + v0.y) + (v0.z + v0.w);
            s1 += (v1.x + v1.y) + (v1.z + v1.w);
            s2 += (v2.x + v2.y) + (v2.z + v2.w);
            s3 += (v3.x + v3.y) + (v3.z + v3.w);
        }
        for (; idx < 512000; idx += 65536) {
            float4 v = __ldg(&src[idx]);
            s0 += (v.x + v.y) + (v.z + v.w);
        }
        float s = (s0 + s1) + (s2 + s3);
        if (s == 1.2345678e38f) g_sink = s;   // never true; keeps loads
        return;
    }

    const int i    = blockIdx.x >> 2;
    const int jc   = blockIdx.x & 3;
    const int jbase = jc * 640;

    s_U[tid] = g_U[i * 128 + tid];
    if (tid < 20) s_words[tid] = g_mbits[i * NW + jc * 20 + tid];
    if (tid < Dn) {
        s_pf[tid] = g_pre_f[i * Dn + tid];
        s_wu[tid] = __ldg(&Wu[tid]);
    }
    __syncthreads();

    if (wid == 0) {
        float s = fabsf(s_wu[lane]) + fabsf(s_wu[lane + 32]);
        #pragma unroll
        for (int off = 16; off > 0; off >>= 1)
            s += __shfl_xor_sync(0xffffffffu, s, off);
        if (lane == 0) s_swu = s;
    }
    __syncthreads();
    if (tid == 0) {
        float bnd = __int_as_float(g_maxa_bits) + __int_as_float(g_maxb_bits);
        float b5 = bnd * bnd; b5 = b5 * b5 * bnd;
        s_exact = (0.1333334f * b5 * s_swu >= 1e-4f) ? 1 : 0;
    }

    unsigned flags = 0;
    #pragma unroll
    for (int c = 0; c < 5; c++) {
        const int jl = c * 128 + tid;
        const bool act = ((s_words[jl >> 5] >> (jl & 31)) & 1u) &&
                         (jbase + jl < FH);
        if (act) flags |= (1u << c);
    }
    const int cl = __popc(flags);
    int inc = cl;
    #pragma unroll
    for (int off = 1; off < 32; off <<= 1) {
        int v = __shfl_up_sync(0xffffffffu, inc, off);
        if (lane >= off) inc += v;
    }
    if (lane == 31) s_warpbase[wid + 1] = inc;
    __syncthreads();
    if (tid == 0) {
        s_warpbase[0] = 0;
        #pragma unroll
        for (int w = 1; w <= 4; w++) s_warpbase[w] += s_warpbase[w - 1];
    }
    __syncthreads();
    {
        int off = s_warpbase[wid] + inc - cl;
        #pragma unroll
        for (int c = 0; c < 5; c++)
            if ((flags >> c) & 1u)
                s_jlist[off++] = (unsigned short)(c * 128 + tid);
    }
    __syncthreads();
    const int cnt = s_warpbase[4];

    float wsum = 0.f;
    if (!s_exact) {
        const ull* P1u = (const ull*)s_U;
        const ull* P2u = (const ull*)(s_U + 64);
        for (int m = tid; m < cnt; m += 128) {
            const int j = jbase + (int)s_jlist[m];
            const float4* vr = (const float4*)(g_V + j * 128);
            ull acc = 0ull;
            #pragma unroll
            for (int q = 0; q < 16; q++) {
                float4 b4 = __ldg(vr + q);
                ull b01 = pk2(b4.x, b4.y);
                ull b23 = pk2(b4.z, b4.w);
                ull t01 = f2fma(P2u[2 * q],     b01, P1u[2 * q]);
                ull t23 = f2fma(P2u[2 * q + 1], b23, P1u[2 * q + 1]);
                acc = f2fma(t01, b01, acc);
                acc = f2fma(t23, b23, acc);
            }
            float d0, d1; upk2(acc, d0, d1);
            float e = __expf(__ldg(&g_B[j]) - (d0 + d1));
            s_elist[m] = e;
            wsum += e;
        }
    } else {
        for (int m = tid; m < cnt; m += 128) {
            const int j = jbase + (int)s_jlist[m];
            const float* vr = g_V + j * 128;
            float s = 0.f;
            for (int k = 0; k < Dn; k++)
                s += tanhf(s_pf[k] + vr[k]) * s_wu[k];
            float e = expf(s);
            s_elist[m] = e;
            wsum += e;
        }
    }
    #pragma unroll
    for (int off = 16; off > 0; off >>= 1)
        wsum += __shfl_xor_sync(0xffffffffu, wsum, off);
    if (lane == 0) s_wsum[wid] = wsum;
    __syncthreads();
    if (tid == 0)
        g_ssum_part[i][jc] = (s_wsum[0] + s_wsum[1]) + (s_wsum[2] + s_wsum[3]);

    {
        const int gg = tid >> 6;
        const int k  = tid & 63;
        float a0 = 0.f, a1 = 0.f, a2 = 0.f, a3 = 0.f;
        float a4 = 0.f, a5 = 0.f, a6 = 0.f, a7 = 0.f;
        int m = gg;
        for (; m + 14 < cnt; m += 16) {
            a0 += s_elist[m]      * __ldg(full_row(feat, hid, jbase + (int)s_jlist[m])      + k);
            a1 += s_elist[m + 2]  * __ldg(full_row(feat, hid, jbase + (int)s_jlist[m + 2])  + k);
            a2 += s_elist[m + 4]  * __ldg(full_row(feat, hid, jbase + (int)s_jlist[m + 4])  + k);
            a3 += s_elist[m + 6]  * __ldg(full_row(feat, hid, jbase + (int)s_jlist[m + 6])  + k);
            a4 += s_elist[m + 8]  * __ldg(full_row(feat, hid, jbase + (int)s_jlist[m + 8])  + k);
            a5 += s_elist[m + 10] * __ldg(full_row(feat, hid, jbase + (int)s_jlist[m + 10]) + k);
            a6 += s_elist[m + 12] * __ldg(full_row(feat, hid, jbase + (int)s_jlist[m + 12]) + k);
            a7 += s_elist[m + 14] * __ldg(full_row(feat, hid, jbase + (int)s_jlist[m + 14]) + k);
        }
        for (; m < cnt; m += 2)
            a0 += s_elist[m] * __ldg(full_row(feat, hid, jbase + (int)s_jlist[m]) + k);
        s_part[gg][k] = ((a0 + a1) + (a2 + a3)) + ((a4 + a5) + (a6 + a7));
        __syncthreads();
        if (tid < Dn)
            g_ctx_part[jc][i][tid] = s_part[0][tid] + s_part[1][tid];
    }
}

// ---------------------------------------------------------------------------
// K3: reduce ctx partials. 125 blocks x 256.
// ---------------------------------------------------------------------------
__global__ __launch_bounds__(256) void k3()
{
    const int i = blockIdx.x * 4 + (threadIdx.x >> 6);
    const int k = threadIdx.x & 63;
    float ss = (g_ssum_part[i][0] + g_ssum_part[i][1]) +
               (g_ssum_part[i][2] + g_ssum_part[i][3]);
    const float inv = (ss > 0.f) ? (1.0f / ss) : 1.0f;
    float c = (g_ctx_part[0][i][k] + g_ctx_part[1][i][k]) +
              (g_ctx_part[2][i][k] + g_ctx_part[3][i][k]);
    g_ctx[i * Dn + k] = c * inv;
}

// ---------------------------------------------------------------------------
// K4a: out partials = values @ ctx, split-f by 10.
// 640 blocks (64 rowblocks x 10 fsplits) x 256 threads.
// Block tile 64 rows x 64 cols; thread = 2 rows x 8 cols (8 FFMA2 / f).
// Double-buffered smem tiles of TFQ=10 f. ~3-4 CTAs/SM resident.
// ---------------------------------------------------------------------------
__global__ __launch_bounds__(256) void k4a(const float* __restrict__ values)
{
    __shared__ __align__(16) float s_val[2][64][TFQ];
    __shared__ __align__(16) float s_ctx[2][TFQ][Dn];

    const int rb    = blockIdx.x / FSPLIT;     // 0..63
    const int fs    = blockIdx.x % FSPLIT;     // 0..9
    const int row0  = rb * 64;
    const int fbase = fs * FCH;
    const int tid   = threadIdx.x;
    const int rg    = tid >> 3;                // 0..31 (2 rows each)
    const int cg    = tid & 7;                 // 0..7  (8 cols each)
    const int r0    = rg * 2;
    const int c0    = cg * 8;

    // loader regs: values 64 rows x 5 float2 = 320 float2/tile;
    //              ctx 10*16 = 160 float4/tile
    float2 vreg0, vreg1;
    float4 creg;
    const int vr0 = tid / 5, vc0 = tid - vr0 * 5;                 // q0 = tid < 320 always (tid<256)
    const int q1 = tid + 256;
    const int vr1 = q1 / 5, vc1 = q1 - vr1 * 5;                   // valid if q1 < 320

    #define K4_LOAD(t)                                                        \
        do {                                                                  \
            vreg0 = *(const float2*)&values[(size_t)(row0 + vr0) * Fn +       \
                                            fbase + (t) * TFQ + vc0 * 2];     \
            if (q1 < 320)                                                     \
                vreg1 = *(const float2*)&values[(size_t)(row0 + vr1) * Fn +   \
                                                fbase + (t) * TFQ + vc1 * 2]; \
            if (tid < 160) {                                                  \
                int f = tid >> 4, c4 = tid & 15;                              \
                creg = *(const float4*)&g_ctx[(fbase + (t) * TFQ + f) * Dn +  \
                                              c4 * 4];                        \
            }                                                                 \
        } while (0)

    #define K4_STORE(buf)                                                    \
        do {                                                                 \
            *(float2*)&s_val[buf][vr0][vc0 * 2] = vreg0;                     \
            if (q1 < 320) *(float2*)&s_val[buf][vr1][vc1 * 2] = vreg1;       \
            if (tid < 160) {                                                 \
                int f = tid >> 4, c4 = tid & 15;                             \
                *(float4*)&s_ctx[buf][f][c4 * 4] = creg;                     \
            }                                                                \
        } while (0)

    ull acc[8];
    #pragma unroll
    for (int q = 0; q < 8; q++) acc[q] = 0ull;

    K4_LOAD(0);
    K4_STORE(0);
    __syncthreads();

    #pragma unroll
    for (int t = 0; t < FCH / TFQ; t++) {       // 5 tiles
        if (t + 1 < FCH / TFQ) K4_LOAD(t + 1);
        const int b = t & 1;
        #pragma unroll
        for (int f = 0; f < TFQ; f++) {
            float v0 = s_val[b][r0 + 0][f];
            float v1 = s_val[b][r0 + 1][f];
            const ull* cp = (const ull*)&s_ctx[b][f][c0];
            ull cA = cp[0], cB = cp[1], cC = cp[2], cD = cp[3];
            ull p0 = pk2(v0, v0), p1 = pk2(v1, v1);
            acc[0] = f2fma(p0, cA, acc[0]);
            acc[1] = f2fma(p0, cB, acc[1]);
            acc[2] = f2fma(p0, cC, acc[2]);
            acc[3] = f2fma(p0, cD, acc[3]);
            acc[4] = f2fma(p1, cA, acc[4]);
            acc[5] = f2fma(p1, cB, acc[5]);
            acc[6] = f2fma(p1, cC, acc[6]);
            acc[7] = f2fma(p1, cD, acc[7]);
        }
        __syncthreads();
        if (t + 1 < FCH / TFQ) {
            K4_STORE((t + 1) & 1);
        }
        __syncthreads();
    }

    #pragma unroll
    for (int r = 0; r < 2; r++) {
        float a, b, c, d, e, f2, g, h;
        upk2(acc[r * 4 + 0], a, b);
        upk2(acc[r * 4 + 1], c, d);
        upk2(acc[r * 4 + 2], e, f2);
        upk2(acc[r * 4 + 3], g, h);
        float* dst = &g_out_part[fs][row0 + r0 + r][c0];
        *(float4*)dst       = make_float4(a, b, c, d);
        *(float4*)(dst + 4) = make_float4(e, f2, g, h);
    }
}

// ---------------------------------------------------------------------------
// K4b: out = sum of 10 partials (fixed order). 256 blocks x 256 threads.
// ---------------------------------------------------------------------------
__global__ __launch_bounds__(256) void k4b(float* __restrict__ out)
{
    const int idx = blockIdx.x * 256 + threadIdx.x;     // < 65536 float4
    float4 r = make_float4(0.f, 0.f, 0.f, 0.f);
    #pragma unroll
    for (int s = 0; s < FSPLIT; s++) {
        const float4* p = (const float4*)&g_out_part[s][0][0];
        float4 v = __ldg(&p[idx]);
        r.x += v.x; r.y += v.y; r.z += v.z; r.w += v.w;
    }
    ((float4*)out)[idx] = r;
}

// ---------------------------------------------------------------------------
extern "C" void kernel_launch(void* const* d_in, const int* in_sizes, int n_in,
                              void* d_out, int out_size)
{
    const float* values   = (const float*)d_in[0];
    const float* feat_emb = (const float*)d_in[1];
    const float* hid_emb  = (const float*)d_in[2];
    const float* Ww       = (const float*)d_in[3];
    const float* bw       = (const float*)d_in[4];
    const float* Wu       = (const float*)d_in[5];
    const float* mask     = (const float*)d_in[6];
    float* out            = (float*)d_out;

    k1<<<907, 256>>>(feat_emb, hid_emb, Ww, bw, Wu, mask);
    k2<<<2512, 128>>>(values, feat_emb, hid_emb, Wu);
    k3<<<125, 256>>>();
    k4a<<<640, 256>>>(values);
    k4b<<<256, 256>>>(out);
}

// round 17
// speedup vs baseline: 1.0756x; 1.0756x over previous
#include <cuda_runtime.h>
#include <cuda_bf16.h>
#include <math.h>

#define Fn 500
#define Hn 2000
#define FH 2500
#define Dn 64
#define Bn 4096
#define NJC 4            // j-chunks of 640
#define FSPLIT 10
#define FCH 50           // f per split

// Scratch
__device__ __align__(16) float g_U[Fn * 128];     // [P1=wu*a^2 | P2=wu*a]
__device__ __align__(16) float g_V[FH * 128];     // [b | b^2]
__device__ float g_B[FH];
__device__ __align__(16) float g_pre_f[Fn * Dn];
__device__ __align__(16) float g_ctx_part[NJC][Fn][Dn];
__device__ float g_ssum_part[Fn][NJC];
__device__ __align__(16) float g_ctx[Fn * Dn];
__device__ __align__(16) float g_out_part[FSPLIT][Bn][Dn];
__device__ int g_maxa_bits = 0;   // idempotent across replays (same inputs)
__device__ int g_maxb_bits = 0;

typedef unsigned long long ull;
__device__ __forceinline__ ull pk2(float a, float b) {
    ull r; asm("mov.b64 %0, {%1,%2};" : "=l"(r) : "f"(a), "f"(b)); return r;
}
__device__ __forceinline__ void upk2(ull v, float& a, float& b) {
    asm("mov.b64 {%0,%1}, %2;" : "=f"(a), "=f"(b) : "l"(v));
}
__device__ __forceinline__ ull f2fma(ull a, ull b, ull c) {
    ull d; asm("fma.rn.f32x2 %0, %1, %2, %3;" : "=l"(d) : "l"(a), "l"(b), "l"(c)); return d;
}
__device__ __forceinline__ const float* full_row(const float* feat,
                                                 const float* hid, int j) {
    return (j < Fn) ? (feat + j * Dn) : (hid + (j - Fn) * Dn);
}

// ---------------------------------------------------------------------------
// K1: blk 0..624   : pre_w rows -> V=[b,b^2], B_j, maxb
//     blk 625..749 : pre_f rows -> U, pre_f, maxa
// ---------------------------------------------------------------------------
__global__ __launch_bounds__(256) void k1(const float* __restrict__ feat,
                                          const float* __restrict__ hid,
                                          const float* __restrict__ Ww,
                                          const float* __restrict__ bw,
                                          const float* __restrict__ Wu)
{
    __shared__ float sx[4][Dn];
    __shared__ float s_red[8];
    __shared__ float s_rmax[8];

    const int blk  = blockIdx.x;
    const int tid  = threadIdx.x;
    const int g    = tid >> 6;
    const int a    = tid & 63;
    const int wid  = tid >> 5;
    const int lane = tid & 31;

    if (blk < 625) {
        const int row = blk * 4 + g;                    // j: 0..2499
        float v = (row < Fn) ? feat[row * Dn + a] : hid[(row - Fn) * Dn + a];
        sx[g][a] = v;
        __syncthreads();
        float bacc = 0.f;
        #pragma unroll
        for (int k = 0; k < Dn; k++)
            bacc += sx[g][k] * __ldg(&Ww[(Dn + k) * Dn + a]);
        const float wua = __ldg(&Wu[a]);
        const float b2 = bacc * bacc;
        g_V[row * 128 + a]      = bacc;
        g_V[row * 128 + 64 + a] = b2;
        float term = wua * (bacc - bacc * b2 * 0.33333334f);
        float mm = fabsf(bacc);
        #pragma unroll
        for (int off = 16; off > 0; off >>= 1) {
            term += __shfl_xor_sync(0xffffffffu, term, off);
            mm = fmaxf(mm, __shfl_xor_sync(0xffffffffu, mm, off));
        }
        if (lane == 0) { s_red[wid] = term; s_rmax[wid] = mm; }
        __syncthreads();
        if (tid < 4)
            g_B[blk * 4 + tid] = s_red[2 * tid] + s_red[2 * tid + 1];
        if (tid == 0) {
            float mx = fmaxf(fmaxf(s_rmax[0], s_rmax[1]),
                             fmaxf(s_rmax[2], s_rmax[3]));
            mx = fmaxf(mx, fmaxf(fmaxf(s_rmax[4], s_rmax[5]),
                                 fmaxf(s_rmax[6], s_rmax[7])));
            atomicMax(&g_maxb_bits, __float_as_int(mx));
        }
    } else {
        const int row = (blk - 625) * 4 + g;            // i: 0..499
        sx[g][a] = feat[row * Dn + a];
        __syncthreads();
        float av = __ldg(&bw[a]);
        #pragma unroll
        for (int k = 0; k < Dn; k++)
            av += sx[g][k] * __ldg(&Ww[k * Dn + a]);
        const float wua = __ldg(&Wu[a]);
        g_pre_f[row * Dn + a]   = av;
        g_U[row * 128 + a]      = wua * av * av;
        g_U[row * 128 + 64 + a] = wua * av;
        float mm = fabsf(av);
        #pragma unroll
        for (int off = 16; off > 0; off >>= 1)
            mm = fmaxf(mm, __shfl_xor_sync(0xffffffffu, mm, off));
        if (lane == 0) s_rmax[wid] = mm;
        __syncthreads();
        if (tid == 0) {
            float mx = fmaxf(fmaxf(s_rmax[0], s_rmax[1]),
                             fmaxf(s_rmax[2], s_rmax[3]));
            mx = fmaxf(mx, fmaxf(fmaxf(s_rmax[4], s_rmax[5]),
                                 fmaxf(s_rmax[6], s_rmax[7])));
            atomicMax(&g_maxa_bits, __float_as_int(mx));
        }
    }
}

// ---------------------------------------------------------------------------
// K2: 2000 blocks = 500 i x 4 j-chunks; compaction directly from mask.
// ---------------------------------------------------------------------------
__global__ __launch_bounds__(128) void k2(const float* __restrict__ mask,
                                          const float* __restrict__ feat,
                                          const float* __restrict__ hid,
                                          const float* __restrict__ Wu)
{
    __shared__ __align__(16) float s_U[128];
    __shared__ __align__(16) float s_pf[Dn];
    __shared__ __align__(16) float s_wu[Dn];
    __shared__ unsigned short s_jlist[640];
    __shared__ float s_elist[640];
    __shared__ int   s_warpbase[5];
    __shared__ float s_wsum[4];
    __shared__ float s_part[2][Dn];
    __shared__ float s_swu;
    __shared__ int   s_exact;

    const int tid  = threadIdx.x;
    const int wid  = tid >> 5;
    const int lane = tid & 31;
    const int i    = blockIdx.x >> 2;
    const int jc   = blockIdx.x & 3;
    const int jbase = jc * 640;

    s_U[tid] = g_U[i * 128 + tid];
    if (tid < Dn) {
        s_pf[tid] = g_pre_f[i * Dn + tid];
        s_wu[tid] = __ldg(&Wu[tid]);
    }
    __syncthreads();

    if (wid == 0) {
        float s = fabsf(s_wu[lane]) + fabsf(s_wu[lane + 32]);
        #pragma unroll
        for (int off = 16; off > 0; off >>= 1)
            s += __shfl_xor_sync(0xffffffffu, s, off);
        if (lane == 0) s_swu = s;
    }
    __syncthreads();
    if (tid == 0) {
        float bnd = __int_as_float(g_maxa_bits) + __int_as_float(g_maxb_bits);
        float b5 = bnd * bnd; b5 = b5 * b5 * bnd;
        s_exact = (0.1333334f * b5 * s_swu >= 1e-4f) ? 1 : 0;
    }

    // compaction from mask (bounds-guarded loads)
    const float* mrow = mask + (size_t)i * FH + jbase;
    unsigned flags = 0;
    #pragma unroll
    for (int c = 0; c < 5; c++) {
        const int jl = c * 128 + tid;
        if ((jbase + jl < FH) && (__ldg(&mrow[jl]) != 0.0f))
            flags |= (1u << c);
    }
    const int cl = __popc(flags);
    int inc = cl;
    #pragma unroll
    for (int off = 1; off < 32; off <<= 1) {
        int v = __shfl_up_sync(0xffffffffu, inc, off);
        if (lane >= off) inc += v;
    }
    if (lane == 31) s_warpbase[wid + 1] = inc;
    __syncthreads();
    if (tid == 0) {
        s_warpbase[0] = 0;
        #pragma unroll
        for (int w = 1; w <= 4; w++) s_warpbase[w] += s_warpbase[w - 1];
    }
    __syncthreads();
    {
        int off = s_warpbase[wid] + inc - cl;
        #pragma unroll
        for (int c = 0; c < 5; c++)
            if ((flags >> c) & 1u)
                s_jlist[off++] = (unsigned short)(c * 128 + tid);
    }
    __syncthreads();
    const int cnt = s_warpbase[4];

    float wsum = 0.f;
    if (!s_exact) {
        const ull* P1u = (const ull*)s_U;
        const ull* P2u = (const ull*)(s_U + 64);
        for (int m = tid; m < cnt; m += 128) {
            const int j = jbase + (int)s_jlist[m];
            const float4* vr = (const float4*)(g_V + j * 128);
            ull acc = 0ull;
            #pragma unroll
            for (int q = 0; q < 16; q++) {
                float4 b4 = __ldg(vr + q);
                ull b01 = pk2(b4.x, b4.y);
                ull b23 = pk2(b4.z, b4.w);
                ull t01 = f2fma(P2u[2 * q],     b01, P1u[2 * q]);
                ull t23 = f2fma(P2u[2 * q + 1], b23, P1u[2 * q + 1]);
                acc = f2fma(t01, b01, acc);
                acc = f2fma(t23, b23, acc);
            }
            float d0, d1; upk2(acc, d0, d1);
            float e = __expf(__ldg(&g_B[j]) - (d0 + d1));
            s_elist[m] = e;
            wsum += e;
        }
    } else {
        for (int m = tid; m < cnt; m += 128) {
            const int j = jbase + (int)s_jlist[m];
            const float* vr = g_V + j * 128;
            float s = 0.f;
            for (int k = 0; k < Dn; k++)
                s += tanhf(s_pf[k] + vr[k]) * s_wu[k];
            float e = expf(s);
            s_elist[m] = e;
            wsum += e;
        }
    }
    #pragma unroll
    for (int off = 16; off > 0; off >>= 1)
        wsum += __shfl_xor_sync(0xffffffffu, wsum, off);
    if (lane == 0) s_wsum[wid] = wsum;
    __syncthreads();
    if (tid == 0)
        g_ssum_part[i][jc] = (s_wsum[0] + s_wsum[1]) + (s_wsum[2] + s_wsum[3]);

    {
        const int gg = tid >> 6;
        const int k  = tid & 63;
        float a0 = 0.f, a1 = 0.f, a2 = 0.f, a3 = 0.f;
        float a4 = 0.f, a5 = 0.f, a6 = 0.f, a7 = 0.f;
        int m = gg;
        for (; m + 14 < cnt; m += 16) {
            a0 += s_elist[m]      * __ldg(full_row(feat, hid, jbase + (int)s_jlist[m])      + k);
            a1 += s_elist[m + 2]  * __ldg(full_row(feat, hid, jbase + (int)s_jlist[m + 2])  + k);
            a2 += s_elist[m + 4]  * __ldg(full_row(feat, hid, jbase + (int)s_jlist[m + 4])  + k);
            a3 += s_elist[m + 6]  * __ldg(full_row(feat, hid, jbase + (int)s_jlist[m + 6])  + k);
            a4 += s_elist[m + 8]  * __ldg(full_row(feat, hid, jbase + (int)s_jlist[m + 8])  + k);
            a5 += s_elist[m + 10] * __ldg(full_row(feat, hid, jbase + (int)s_jlist[m + 10]) + k);
            a6 += s_elist[m + 12] * __ldg(full_row(feat, hid, jbase + (int)s_jlist[m + 12]) + k);
            a7 += s_elist[m + 14] * __ldg(full_row(feat, hid, jbase + (int)s_jlist[m + 14]) + k);
        }
        for (; m < cnt; m += 2)
            a0 += s_elist[m] * __ldg(full_row(feat, hid, jbase + (int)s_jlist[m]) + k);
        s_part[gg][k] = ((a0 + a1) + (a2 + a3)) + ((a4 + a5) + (a6 + a7));
        __syncthreads();
        if (tid < Dn)
            g_ctx_part[jc][i][tid] = s_part[0][tid] + s_part[1][tid];
    }
}

// ---------------------------------------------------------------------------
// K3: reduce ctx partials. 125 blocks x 256.
// ---------------------------------------------------------------------------
__global__ __launch_bounds__(256) void k3()
{
    const int i = blockIdx.x * 4 + (threadIdx.x >> 6);
    const int k = threadIdx.x & 63;
    float ss = (g_ssum_part[i][0] + g_ssum_part[i][1]) +
               (g_ssum_part[i][2] + g_ssum_part[i][3]);
    const float inv = (ss > 0.f) ? (1.0f / ss) : 1.0f;
    float c = (g_ctx_part[0][i][k] + g_ctx_part[1][i][k]) +
              (g_ctx_part[2][i][k] + g_ctx_part[3][i][k]);
    g_ctx[i * Dn + k] = c * inv;
}

// ---------------------------------------------------------------------------
// K4a: out partials = values @ ctx, split-f by 10.
// 640 blocks x 256 threads. Block = 64 rows x 64 cols x 50 f.
// ONE-SHOT load phase (~11 independent loads/thread), single sync,
// then barrier-free compute. Thread = 2 rows x 8 cols.
// ---------------------------------------------------------------------------
#define VPAD 52
__global__ __launch_bounds__(256) void k4a(const float* __restrict__ values)
{
    __shared__ __align__(16) float s_val[64][VPAD];   // [row][f], padded
    __shared__ __align__(16) float s_ctx[FCH][Dn];    // [f][col]

    const int rb    = blockIdx.x / FSPLIT;     // 0..63
    const int fs    = blockIdx.x % FSPLIT;     // 0..9
    const int row0  = rb * 64;
    const int fbase = fs * FCH;
    const int tid   = threadIdx.x;
    const int rg    = tid >> 3;                // 0..31
    const int cg    = tid & 7;                 // 0..7
    const int r0    = rg * 2;
    const int c0    = cg * 8;

    // ---- one-shot cooperative load: values 1600 float2, ctx 800 float4
    {
        float2 v[7];
        float4 c[4];
        #pragma unroll
        for (int u = 0; u < 7; u++) {
            int q = tid + u * 256;
            if (q < 1600) {
                int r = q / 25, fc = q - r * 25;
                v[u] = *(const float2*)&values[(size_t)(row0 + r) * Fn +
                                               fbase + fc * 2];
            }
        }
        #pragma unroll
        for (int u = 0; u < 4; u++) {
            int q = tid + u * 256;
            if (q < 800) {
                int f = q >> 4, c4 = q & 15;
                c[u] = *(const float4*)&g_ctx[(fbase + f) * Dn + c4 * 4];
            }
        }
        #pragma unroll
        for (int u = 0; u < 7; u++) {
            int q = tid + u * 256;
            if (q < 1600) {
                int r = q / 25, fc = q - r * 25;
                s_val[r][fc * 2]     = v[u].x;
                s_val[r][fc * 2 + 1] = v[u].y;
            }
        }
        #pragma unroll
        for (int u = 0; u < 4; u++) {
            int q = tid + u * 256;
            if (q < 800) {
                int f = q >> 4, c4 = q & 15;
                *(float4*)&s_ctx[f][c4 * 4] = c[u];
            }
        }
    }
    __syncthreads();

    // ---- barrier-free compute: 50 f x 8 FFMA2
    ull acc[8];
    #pragma unroll
    for (int q = 0; q < 8; q++) acc[q] = 0ull;

    #pragma unroll 10
    for (int f = 0; f < FCH; f++) {
        float v0 = s_val[r0 + 0][f];
        float v1 = s_val[r0 + 1][f];
        const ull* cp = (const ull*)&s_ctx[f][c0];
        ull cA = cp[0], cB = cp[1], cC = cp[2], cD = cp[3];
        ull p0 = pk2(v0, v0), p1 = pk2(v1, v1);
        acc[0] = f2fma(p0, cA, acc[0]);
        acc[1] = f2fma(p0, cB, acc[1]);
        acc[2] = f2fma(p0, cC, acc[2]);
        acc[3] = f2fma(p0, cD, acc[3]);
        acc[4] = f2fma(p1, cA, acc[4]);
        acc[5] = f2fma(p1, cB, acc[5]);
        acc[6] = f2fma(p1, cC, acc[6]);
        acc[7] = f2fma(p1, cD, acc[7]);
    }

    #pragma unroll
    for (int r = 0; r < 2; r++) {
        float a, b, c, d, e, f2, g, h;
        upk2(acc[r * 4 + 0], a, b);
        upk2(acc[r * 4 + 1], c, d);
        upk2(acc[r * 4 + 2], e, f2);
        upk2(acc[r * 4 + 3], g, h);
        float* dst = &g_out_part[fs][row0 + r0 + r][c0];
        *(float4*)dst       = make_float4(a, b, c, d);
        *(float4*)(dst + 4) = make_float4(e, f2, g, h);
    }
}

// ---------------------------------------------------------------------------
// K4b: out = sum of 10 partials (fixed order). 256 blocks x 256 threads.
// ---------------------------------------------------------------------------
__global__ __launch_bounds__(256) void k4b(float* __restrict__ out)
{
    const int idx = blockIdx.x * 256 + threadIdx.x;     // < 65536 float4
    float4 r = make_float4(0.f, 0.f, 0.f, 0.f);
    #pragma unroll
    for (int s = 0; s < FSPLIT; s++) {
        const float4* p = (const float4*)&g_out_part[s][0][0];
        float4 v = __ldg(&p[idx]);
        r.x += v.x; r.y += v.y; r.z += v.z; r.w += v.w;
    }
    ((float4*)out)[idx] = r;
}

// ---------------------------------------------------------------------------
extern "C" void kernel_launch(void* const* d_in, const int* in_sizes, int n_in,
                              void* d_out, int out_size)
{
    const float* values   = (const float*)d_in[0];
    const float* feat_emb = (const float*)d_in[1];
    const float* hid_emb  = (const float*)d_in[2];
    const float* Ww       = (const float*)d_in[3];
    const float* bw       = (const float*)d_in[4];
    const float* Wu       = (const float*)d_in[5];
    const float* mask     = (const float*)d_in[6];
    float* out            = (float*)d_out;

    k1<<<750, 256>>>(feat_emb, hid_emb, Ww, bw, Wu);
    k2<<<2000, 128>>>(mask, feat_emb, hid_emb, Wu);
    k3<<<125, 256>>>();
    k4a<<<640, 256>>>(values);
    k4b<<<256, 256>>>(out);
}